// round 4
// baseline (speedup 1.0000x reference)
#include <cuda_runtime.h>
#include <math.h>

#define N_NODES 100000
#define N_EDGES 1000000
#define F 32
#define DFEAT 160            // 5 segments x 32
#define BM 128               // GEMM M tile
#define CHUNK 1024
#define NCHUNK ((N_NODES + CHUNK - 1) / CHUNK)   // 98

// ---------------- scratch (device globals; no allocation) ----------------
__device__ __align__(16) float g_deg[2 * N_NODES];        // [deg_out | deg_in]
__device__ __align__(16) int   g_hist[N_NODES];
__device__ __align__(16) int   g_ptr[N_NODES];
__device__ __align__(16) int   g_bsum[NCHUNK];
__device__ __align__(16) int   g_boff[NCHUNK];
__device__ __align__(16) int   g_ssrc[N_EDGES];           // edges sorted by src
__device__ __align__(16) int   g_sdst[N_EDGES];
__device__ __align__(16) float g_sno[N_EDGES];
__device__ __align__(16) float g_sni[N_EDGES];
__device__ __align__(16) float g_T1o[N_NODES * F];
__device__ __align__(16) float g_T1i[N_NODES * F];
__device__ __align__(16) float g_P2o[N_NODES * F];
__device__ __align__(16) float g_P2i[N_NODES * F];
__device__ __align__(16) float g_W[DFEAT * 64];           // [f][64]: cols 0-31 Wz_eff, 32-63 Wh_eff

// ---------------- helpers ----------------
__device__ __forceinline__ void red4(float* p, float a, float b, float c, float d) {
    asm volatile("red.global.add.v4.f32 [%0], {%1,%2,%3,%4};"
                 :: "l"(p), "f"(a), "f"(b), "f"(c), "f"(d) : "memory");
}

// ---------------- sort pipeline ----------------
__global__ void histdeg_kernel(const int* __restrict__ src, const int* __restrict__ dst,
                               const float* __restrict__ ew) {
    int e = blockIdx.x * blockDim.x + threadIdx.x;
    if (e >= N_EDGES) return;
    int s = src[e], d = dst[e];
    float w = ew[e];
    atomicAdd(&g_hist[s], 1);
    atomicAdd(&g_deg[s], w);
    atomicAdd(&g_deg[N_NODES + d], w);
}

// per-chunk exclusive scan of hist -> g_ptr; chunk totals -> g_bsum
__global__ void scan1_kernel() {
    int chunk = blockIdx.x;
    int tid = threadIdx.x;
    int bin = chunk * CHUNK + tid;
    int v = (bin < N_NODES) ? g_hist[bin] : 0;
    int lane = tid & 31, wid = tid >> 5;
    int x = v;
#pragma unroll
    for (int o = 1; o < 32; o <<= 1) {
        int y = __shfl_up_sync(0xffffffffu, x, o);
        if (lane >= o) x += y;
    }
    __shared__ int wsum[32];
    if (lane == 31) wsum[wid] = x;
    __syncthreads();
    if (wid == 0) {
        int w = wsum[lane];
#pragma unroll
        for (int o = 1; o < 32; o <<= 1) {
            int y = __shfl_up_sync(0xffffffffu, w, o);
            if (lane >= o) w += y;
        }
        wsum[lane] = w;
    }
    __syncthreads();
    int incl = x + (wid > 0 ? wsum[wid - 1] : 0);
    if (bin < N_NODES) g_ptr[bin] = incl - v;   // exclusive within chunk
    if (tid == CHUNK - 1) g_bsum[chunk] = incl; // chunk total
}

// exclusive scan of 98 chunk totals -> g_boff
__global__ void scan2_kernel() {
    int tid = threadIdx.x;   // 128 threads
    int v = (tid < NCHUNK) ? g_bsum[tid] : 0;
    int lane = tid & 31, wid = tid >> 5;
    int x = v;
#pragma unroll
    for (int o = 1; o < 32; o <<= 1) {
        int y = __shfl_up_sync(0xffffffffu, x, o);
        if (lane >= o) x += y;
    }
    __shared__ int ws[4];
    if (lane == 31) ws[wid] = x;
    __syncthreads();
    int off = 0;
    for (int w2 = 0; w2 < wid; w2++) off += ws[w2];
    int incl = x + off;
    if (tid < NCHUNK) g_boff[tid] = incl - v;
}

// place edges into src-sorted order, computing norms inline
__global__ void scatter_kernel(const int* __restrict__ src, const int* __restrict__ dst,
                               const float* __restrict__ ew) {
    int e = blockIdx.x * blockDim.x + threadIdx.x;
    if (e >= N_EDGES) return;
    int s = src[e], d = dst[e];
    float w = ew[e];
    float no = w / g_deg[s];
    float ni = w / g_deg[N_NODES + d];
    int p = atomicAdd(&g_ptr[s], 1) + g_boff[s >> 10];
    g_ssrc[p] = s;
    g_sdst[p] = d;
    g_sno[p] = no;
    g_sni[p] = ni;
}

// ---------------- propagation over src-sorted edges ----------------
// STEP 0: Gout=Gin=X (kernel arg), Oout=g_T1o, Oin=g_T1i
// STEP 1: Gout=g_T1o, Gin=g_T1i,   Oout=g_P2o, Oin=g_P2i
// All scratch buffers are bound in DEVICE code (host-side symbol decay is invalid!).
template <int STEP>
__global__ void prop_sorted_kernel(const float* __restrict__ X) {
    const float* Gout = (STEP == 0) ? X : (const float*)g_T1o;
    const float* Gin  = (STEP == 0) ? X : (const float*)g_T1i;
    float* Oout = (STEP == 0) ? g_T1o : g_P2o;
    float* Oin  = (STEP == 0) ? g_T1i : g_P2i;

    int t = blockIdx.x * blockDim.x + threadIdx.x;
    int run = t >> 3, q = t & 7;
    if (run >= N_EDGES / 4) return;
    int4   s4  = ((const int4*)g_ssrc)[run];
    int4   d4  = ((const int4*)g_sdst)[run];
    float4 no4 = ((const float4*)g_sno)[run];
    float4 ni4 = ((const float4*)g_sni)[run];
    int   s[4]  = { s4.x, s4.y, s4.z, s4.w };
    int   d[4]  = { d4.x, d4.y, d4.z, d4.w };
    float no[4] = { no4.x, no4.y, no4.z, no4.w };
    float ni[4] = { ni4.x, ni4.y, ni4.z, ni4.w };

    float4 xo = ((const float4*)Gout)[s[0] * 8 + q];
    int last = s[0];
    float4 acc = make_float4(0.f, 0.f, 0.f, 0.f);
    int cur = s[0];

#pragma unroll
    for (int i = 0; i < 4; i++) {
        if (s[i] != last) { xo = ((const float4*)Gout)[s[i] * 8 + q]; last = s[i]; }
        red4(&Oout[d[i] * F + q * 4], no[i] * xo.x, no[i] * xo.y, no[i] * xo.z, no[i] * xo.w);

        float4 xi = ((const float4*)Gin)[d[i] * 8 + q];
        if (s[i] != cur) {
            red4(&Oin[cur * F + q * 4], acc.x, acc.y, acc.z, acc.w);
            acc = make_float4(0.f, 0.f, 0.f, 0.f);
            cur = s[i];
        }
        acc.x += ni[i] * xi.x;
        acc.y += ni[i] * xi.y;
        acc.z += ni[i] * xi.z;
        acc.w += ni[i] * xi.w;
    }
    red4(&Oin[cur * F + q * 4], acc.x, acc.y, acc.z, acc.w);
}

// ---------------- weight prep ----------------
__global__ void wprep_kernel(const float* __restrict__ Wz, const float* __restrict__ Wh) {
    int idx = blockIdx.x * blockDim.x + threadIdx.x;
    if (idx >= 2 * DFEAT * F) return;
    int gate = idx / (DFEAT * F);
    int rem  = idx % (DFEAT * F);
    int f = rem / F, j = rem % F;
    int seg = f >> 5, r = f & 31;
    const float* W = gate ? Wh : Wz;
    float v;
    if (seg == 0)      v = W[(0 * 64 + r) * 32 + j] + W[(3 * 64 + r) * 32 + j]
                         - W[(2 * 64 + r) * 32 + j] - W[(5 * 64 + r) * 32 + j];
    else if (seg == 1) v = W[(1 * 64 + r) * 32 + j];
    else if (seg == 2) v = W[(4 * 64 + r) * 32 + j];
    else if (seg == 3) v = 2.f * W[(2 * 64 + r) * 32 + j];
    else               v = 2.f * W[(5 * 64 + r) * 32 + j];
    g_W[f * 64 + gate * 32 + j] = v;
}

// ---------------- fused GEMM + GRU epilogue ----------------
__global__ __launch_bounds__(128) void gemm_kernel(
    const float* __restrict__ X,
    const float* __restrict__ bz, const float* __restrict__ bh,
    const float* __restrict__ wl, const float* __restrict__ bl,
    float* __restrict__ out)
{
    __shared__ float As[32][BM + 1];
    __shared__ float Bs[32][64];

    int tid = threadIdx.x;
    int tx = tid & 7;
    int ty = tid >> 3;
    int m0 = ty * 8;
    int blockm = blockIdx.x * BM;

    float acc[8][8];
#pragma unroll
    for (int i = 0; i < 8; i++)
#pragma unroll
        for (int j = 0; j < 8; j++) acc[i][j] = 0.f;

    const float* segp[5] = { X, g_T1o, g_T1i, g_P2o, g_P2i };

    for (int ks = 0; ks < 5; ks++) {
        const float* A = segp[ks];
#pragma unroll
        for (int i = 0; i < 8; i++) {
            int idx = i * 128 + tid;
            int m  = idx >> 3;
            int f4 = idx & 7;
            int node = blockm + m;
            float4 v = (node < N_NODES) ? ((const float4*)A)[node * 8 + f4]
                                        : make_float4(0.f, 0.f, 0.f, 0.f);
            As[f4 * 4 + 0][m] = v.x;
            As[f4 * 4 + 1][m] = v.y;
            As[f4 * 4 + 2][m] = v.z;
            As[f4 * 4 + 3][m] = v.w;
        }
#pragma unroll
        for (int i = 0; i < 4; i++) {
            int idx = i * 128 + tid;
            ((float4*)Bs)[idx] = ((const float4*)g_W)[ks * 512 + idx];
        }
        __syncthreads();

#pragma unroll 4
        for (int kk = 0; kk < 32; kk++) {
            float a[8];
#pragma unroll
            for (int i = 0; i < 8; i++) a[i] = As[kk][m0 + i];
            float4 vz = *(const float4*)&Bs[kk][tx * 4];
            float4 vh = *(const float4*)&Bs[kk][32 + tx * 4];
            float b[8] = { vz.x, vz.y, vz.z, vz.w, vh.x, vh.y, vh.z, vh.w };
#pragma unroll
            for (int i = 0; i < 8; i++)
#pragma unroll
                for (int j = 0; j < 8; j++)
                    acc[i][j] = fmaf(a[i], b[j], acc[i][j]);
        }
        __syncthreads();
    }

    float bzv[4], bhv[4], wlv[4];
#pragma unroll
    for (int jj = 0; jj < 4; jj++) {
        int j = tx * 4 + jj;
        bzv[jj] = bz[j];
        bhv[jj] = bh[j];
        wlv[jj] = wl[j];
    }
    float bl0 = bl[0];

#pragma unroll
    for (int i = 0; i < 8; i++) {
        float y = 0.f;
#pragma unroll
        for (int jj = 0; jj < 4; jj++) {
            float gz = acc[i][jj] + bzv[jj];
            float gh = acc[i][jj + 4] + bhv[jj];
            float z  = 1.f / (1.f + expf(-gz));
            float ht = tanhf(gh);
            float Hv = (1.f - z) * ht;
            y += fmaxf(Hv, 0.f) * wlv[jj];
        }
        y += __shfl_xor_sync(0xffffffffu, y, 4);
        y += __shfl_xor_sync(0xffffffffu, y, 2);
        y += __shfl_xor_sync(0xffffffffu, y, 1);
        if (tx == 0) {
            int node = blockm + m0 + i;
            if (node < N_NODES) out[node] = y + bl0;
        }
    }
}

// ---------------- launch ----------------
extern "C" void kernel_launch(void* const* d_in, const int* in_sizes, int n_in,
                              void* d_out, int out_size) {
    const float* x  = (const float*)d_in[0];
    const int*   ei = (const int*)d_in[1];
    const float* ew = (const float*)d_in[2];
    const float* Wz = (const float*)d_in[5];
    const float* bz = (const float*)d_in[6];
    const float* Wh = (const float*)d_in[9];
    const float* bh = (const float*)d_in[10];
    const float* Wl = (const float*)d_in[11];
    const float* bl = (const float*)d_in[12];
    float* out = (float*)d_out;

    const int* src = ei;
    const int* dst = ei + N_EDGES;

    void *p_deg, *p_hist, *p_t1o, *p_t1i, *p_p2o, *p_p2i;
    cudaGetSymbolAddress(&p_deg,  g_deg);
    cudaGetSymbolAddress(&p_hist, g_hist);
    cudaGetSymbolAddress(&p_t1o,  g_T1o);
    cudaGetSymbolAddress(&p_t1i,  g_T1i);
    cudaGetSymbolAddress(&p_p2o,  g_P2o);
    cudaGetSymbolAddress(&p_p2i,  g_P2i);

    cudaMemsetAsync(p_deg,  0, 2 * N_NODES * sizeof(float), 0);
    cudaMemsetAsync(p_hist, 0, N_NODES * sizeof(int), 0);
    cudaMemsetAsync(p_t1o,  0, N_NODES * F * sizeof(float), 0);
    cudaMemsetAsync(p_t1i,  0, N_NODES * F * sizeof(float), 0);
    cudaMemsetAsync(p_p2o,  0, N_NODES * F * sizeof(float), 0);
    cudaMemsetAsync(p_p2i,  0, N_NODES * F * sizeof(float), 0);

    histdeg_kernel<<<(N_EDGES + 255) / 256, 256>>>(src, dst, ew);
    scan1_kernel<<<NCHUNK, CHUNK>>>();
    scan2_kernel<<<1, 128>>>();
    scatter_kernel<<<(N_EDGES + 255) / 256, 256>>>(src, dst, ew);

    prop_sorted_kernel<0><<<(2 * N_EDGES + 255) / 256, 256>>>(x);
    prop_sorted_kernel<1><<<(2 * N_EDGES + 255) / 256, 256>>>(x);

    wprep_kernel<<<(2 * DFEAT * F + 255) / 256, 256>>>(Wz, Wh);
    gemm_kernel<<<(N_NODES + BM - 1) / BM, 128>>>(x, bz, bh, Wl, bl, out);
}

// round 5
// speedup vs baseline: 1.0371x; 1.0371x over previous
#include <cuda_runtime.h>
#include <math.h>

#define N_NODES 100000
#define N_EDGES 1000000
#define F 32
#define DFEAT 160            // 5 segments x 32
#define BM 128               // GEMM M tile

typedef unsigned long long u64;

// ---------------- scratch (device globals; no allocation) ----------------
__device__ __align__(16) float g_deg[2 * N_NODES];        // [deg_out | deg_in]
__device__ __align__(16) float g_norm[2 * N_EDGES];       // [norm_out | norm_in]
__device__ __align__(16) float g_T1o[N_NODES * F];
__device__ __align__(16) float g_T1i[N_NODES * F];
__device__ __align__(16) float g_P2o[N_NODES * F];
__device__ __align__(16) float g_P2i[N_NODES * F];
__device__ __align__(16) float g_W[DFEAT * 64];           // [f][64]: cols 0-31 Wz_eff, 32-63 Wh_eff

// ---------------- helpers ----------------
__device__ __forceinline__ void red4(float* p, float a, float b, float c, float d) {
    asm volatile("red.global.add.v4.f32 [%0], {%1,%2,%3,%4};"
                 :: "l"(p), "f"(a), "f"(b), "f"(c), "f"(d) : "memory");
}
__device__ __forceinline__ u64 pack2(float lo, float hi) {
    u64 r; asm("mov.b64 %0, {%1,%2};" : "=l"(r) : "f"(lo), "f"(hi)); return r;
}
__device__ __forceinline__ u64 ffma2(u64 a, u64 b, u64 c) {
    u64 d; asm("fma.rn.f32x2 %0, %1, %2, %3;" : "=l"(d) : "l"(a), "l"(b), "l"(c)); return d;
}
__device__ __forceinline__ float2 unpack2(u64 v) {
    float2 f; asm("mov.b64 {%0,%1}, %2;" : "=f"(f.x), "=f"(f.y) : "l"(v)); return f;
}

// ---------------- kernels ----------------
__global__ void deg_kernel(const int* __restrict__ src, const int* __restrict__ dst,
                           const float* __restrict__ ew) {
    int e = blockIdx.x * blockDim.x + threadIdx.x;
    if (e >= N_EDGES) return;
    float w = ew[e];
    atomicAdd(&g_deg[src[e]], w);
    atomicAdd(&g_deg[N_NODES + dst[e]], w);
}

__global__ void norm_kernel(const int* __restrict__ src, const int* __restrict__ dst,
                            const float* __restrict__ ew) {
    int e = blockIdx.x * blockDim.x + threadIdx.x;
    if (e >= N_EDGES) return;
    float w = ew[e];
    g_norm[e]           = w / g_deg[src[e]];
    g_norm[N_EDGES + e] = w / g_deg[N_NODES + dst[e]];
}

// hop 1: T1o[dst] += norm_out * X[src]; T1i[src] += norm_in * X[dst]
__global__ void prop1_kernel(const float* __restrict__ X,
                             const int* __restrict__ src, const int* __restrict__ dst) {
    long idx = (long)blockIdx.x * blockDim.x + threadIdx.x;
    int e = (int)(idx >> 3);
    if (e >= N_EDGES) return;
    int q = (int)(idx & 7);
    int s = src[e], d = dst[e];
    float no = g_norm[e], ni = g_norm[N_EDGES + e];
    float4 a = ((const float4*)X)[s * 8 + q];
    red4(&g_T1o[d * F + q * 4], a.x * no, a.y * no, a.z * no, a.w * no);
    float4 b = ((const float4*)X)[d * 8 + q];
    red4(&g_T1i[s * F + q * 4], b.x * ni, b.y * ni, b.z * ni, b.w * ni);
}

// hop 2: P2o[dst] += norm_out * T1o[src]; P2i[src] += norm_in * T1i[dst]
__global__ void prop2_kernel(const int* __restrict__ src, const int* __restrict__ dst) {
    long idx = (long)blockIdx.x * blockDim.x + threadIdx.x;
    int e = (int)(idx >> 3);
    if (e >= N_EDGES) return;
    int q = (int)(idx & 7);
    int s = src[e], d = dst[e];
    float no = g_norm[e], ni = g_norm[N_EDGES + e];
    float4 a = ((const float4*)g_T1o)[s * 8 + q];
    red4(&g_P2o[d * F + q * 4], a.x * no, a.y * no, a.z * no, a.w * no);
    float4 b = ((const float4*)g_T1i)[d * 8 + q];
    red4(&g_P2i[s * F + q * 4], b.x * ni, b.y * ni, b.z * ni, b.w * ni);
}

// Build W_eff[160][64].  W layout: [2][3][64][32], only rows <32 matter (H-half is zero).
__global__ void wprep_kernel(const float* __restrict__ Wz, const float* __restrict__ Wh) {
    int idx = blockIdx.x * blockDim.x + threadIdx.x;
    if (idx >= 2 * DFEAT * F) return;
    int gate = idx / (DFEAT * F);
    int rem  = idx % (DFEAT * F);
    int f = rem / F, j = rem % F;
    int seg = f >> 5, r = f & 31;
    const float* W = gate ? Wh : Wz;
    float v;
    if (seg == 0)      v = W[(0 * 64 + r) * 32 + j] + W[(3 * 64 + r) * 32 + j]
                         - W[(2 * 64 + r) * 32 + j] - W[(5 * 64 + r) * 32 + j];
    else if (seg == 1) v = W[(1 * 64 + r) * 32 + j];
    else if (seg == 2) v = W[(4 * 64 + r) * 32 + j];
    else if (seg == 3) v = 2.f * W[(2 * 64 + r) * 32 + j];
    else               v = 2.f * W[(5 * 64 + r) * 32 + j];
    g_W[f * 64 + gate * 32 + j] = v;
}

// Fused GEMM [BM x 160] @ [160 x 64] + GRU epilogue, inner loop in packed f32x2 FMA.
// 128 threads: ty=tid>>3 (16 groups, 8 M-rows each), tx=tid&7 (cols {4tx..4tx+3} of both halves).
__global__ __launch_bounds__(128) void gemm_kernel(
    const float* __restrict__ X,
    const float* __restrict__ bz, const float* __restrict__ bh,
    const float* __restrict__ wl, const float* __restrict__ bl,
    float* __restrict__ out)
{
    __shared__ __align__(16) float As[32][BM + 4];   // stride 132: rows 16B-aligned, LDS.128-able
    __shared__ __align__(16) float Bs[32][64];

    int tid = threadIdx.x;
    int tx = tid & 7;
    int ty = tid >> 3;
    int m0 = ty * 8;
    int blockm = blockIdx.x * BM;

    // acc2[i][jp]: packed pair = cols (2jp, 2jp+1); jp<2 -> z half, jp>=2 -> h half
    u64 acc2[8][4];
#pragma unroll
    for (int i = 0; i < 8; i++)
#pragma unroll
        for (int j = 0; j < 4; j++) acc2[i][j] = 0ull;

    const float* segp[5] = { X, g_T1o, g_T1i, g_P2o, g_P2i };

    for (int ks = 0; ks < 5; ks++) {
        const float* A = segp[ks];
        // A tile: 128 nodes x 32 feats, stored transposed As[kk][m]
#pragma unroll
        for (int i = 0; i < 8; i++) {
            int idx = i * 128 + tid;          // 0..1023
            int m  = idx >> 3;
            int f4 = idx & 7;
            int node = blockm + m;
            float4 v = (node < N_NODES) ? ((const float4*)A)[node * 8 + f4]
                                        : make_float4(0.f, 0.f, 0.f, 0.f);
            As[f4 * 4 + 0][m] = v.x;
            As[f4 * 4 + 1][m] = v.y;
            As[f4 * 4 + 2][m] = v.z;
            As[f4 * 4 + 3][m] = v.w;
        }
        // B tile: 32 x 64 from g_W rows ks*32..ks*32+31 (contiguous)
#pragma unroll
        for (int i = 0; i < 4; i++) {
            int idx = i * 128 + tid;          // float4 index, 0..511
            ((float4*)Bs)[idx] = ((const float4*)g_W)[ks * 512 + idx];
        }
        __syncthreads();

#pragma unroll 4
        for (int kk = 0; kk < 32; kk++) {
            float4 a0 = *(const float4*)&As[kk][m0];
            float4 a1 = *(const float4*)&As[kk][m0 + 4];
            u64 aa[8] = { pack2(a0.x, a0.x), pack2(a0.y, a0.y),
                          pack2(a0.z, a0.z), pack2(a0.w, a0.w),
                          pack2(a1.x, a1.x), pack2(a1.y, a1.y),
                          pack2(a1.z, a1.z), pack2(a1.w, a1.w) };
            float4 vz = *(const float4*)&Bs[kk][tx * 4];
            float4 vh = *(const float4*)&Bs[kk][32 + tx * 4];
            u64 bb[4] = { pack2(vz.x, vz.y), pack2(vz.z, vz.w),
                          pack2(vh.x, vh.y), pack2(vh.z, vh.w) };
#pragma unroll
            for (int i = 0; i < 8; i++)
#pragma unroll
                for (int jp = 0; jp < 4; jp++)
                    acc2[i][jp] = ffma2(aa[i], bb[jp], acc2[i][jp]);
        }
        __syncthreads();
    }

    // epilogue: z = sigmoid(gz), ht = tanh(gh), H = (1-z)*ht, y = relu(H) . wl + bl
    float bzv[4], bhv[4], wlv[4];
#pragma unroll
    for (int jj = 0; jj < 4; jj++) {
        int j = tx * 4 + jj;
        bzv[jj] = bz[j];
        bhv[jj] = bh[j];
        wlv[jj] = wl[j];
    }
    float bl0 = bl[0];

#pragma unroll
    for (int i = 0; i < 8; i++) {
        float2 z01 = unpack2(acc2[i][0]);
        float2 z23 = unpack2(acc2[i][1]);
        float2 h01 = unpack2(acc2[i][2]);
        float2 h23 = unpack2(acc2[i][3]);
        float gzv[4] = { z01.x, z01.y, z23.x, z23.y };
        float ghv[4] = { h01.x, h01.y, h23.x, h23.y };
        float y = 0.f;
#pragma unroll
        for (int jj = 0; jj < 4; jj++) {
            float gz = gzv[jj] + bzv[jj];
            float gh = ghv[jj] + bhv[jj];
            float z  = 1.f / (1.f + expf(-gz));
            float ht = tanhf(gh);
            float Hv = (1.f - z) * ht;
            y += fmaxf(Hv, 0.f) * wlv[jj];
        }
        y += __shfl_xor_sync(0xffffffffu, y, 4);
        y += __shfl_xor_sync(0xffffffffu, y, 2);
        y += __shfl_xor_sync(0xffffffffu, y, 1);
        if (tx == 0) {
            int node = blockm + m0 + i;
            if (node < N_NODES) out[node] = y + bl0;
        }
    }
}

// ---------------- launch ----------------
extern "C" void kernel_launch(void* const* d_in, const int* in_sizes, int n_in,
                              void* d_out, int out_size) {
    const float* x  = (const float*)d_in[0];
    const int*   ei = (const int*)d_in[1];
    const float* ew = (const float*)d_in[2];
    const float* Wz = (const float*)d_in[5];
    const float* bz = (const float*)d_in[6];
    const float* Wh = (const float*)d_in[9];
    const float* bh = (const float*)d_in[10];
    const float* Wl = (const float*)d_in[11];
    const float* bl = (const float*)d_in[12];
    float* out = (float*)d_out;

    const int* src = ei;
    const int* dst = ei + N_EDGES;

    void *p_deg, *p_t1o, *p_t1i, *p_p2o, *p_p2i;
    cudaGetSymbolAddress(&p_deg, g_deg);
    cudaGetSymbolAddress(&p_t1o, g_T1o);
    cudaGetSymbolAddress(&p_t1i, g_T1i);
    cudaGetSymbolAddress(&p_p2o, g_P2o);
    cudaGetSymbolAddress(&p_p2i, g_P2i);

    cudaMemsetAsync(p_deg, 0, 2 * N_NODES * sizeof(float), 0);
    cudaMemsetAsync(p_t1o, 0, N_NODES * F * sizeof(float), 0);
    cudaMemsetAsync(p_t1i, 0, N_NODES * F * sizeof(float), 0);
    cudaMemsetAsync(p_p2o, 0, N_NODES * F * sizeof(float), 0);
    cudaMemsetAsync(p_p2i, 0, N_NODES * F * sizeof(float), 0);

    deg_kernel<<<(N_EDGES + 255) / 256, 256>>>(src, dst, ew);
    norm_kernel<<<(N_EDGES + 255) / 256, 256>>>(src, dst, ew);
    prop1_kernel<<<(N_EDGES * 8 + 255) / 256, 256>>>(x, src, dst);
    prop2_kernel<<<(N_EDGES * 8 + 255) / 256, 256>>>(src, dst);
    wprep_kernel<<<(2 * DFEAT * F + 255) / 256, 256>>>(Wz, Wh);
    gemm_kernel<<<(N_NODES + BM - 1) / BM, 128>>>(x, bz, bh, Wl, bl, out);
}